// round 12
// baseline (speedup 1.0000x reference)
#include <cuda_runtime.h>
#include <cstdint>

// state: [2, 4096, 512] float32. The 4 CNOTs compose into one bit-twiddle
// permutation of the 4096 row indices. GATHER: out[n,i,:] = in[n,src(i),:],
// rows = 512 floats = 2048 B contiguous.
//
// R11: persistent grid-stride form. 148 blocks x 1024 threads = one fat CTA
// per SM (32 warps/SM resident, no CTA churn, no waves). Each thread walks
// the 2^19 32B-chunk space at grid stride with 256-bit v8.f32 accesses.

static __device__ __forceinline__ unsigned src_index(unsigned j) {
    // PAIRS [(0,1),(2,3),(5,2),(11,7)] applied in reverse for the source map
    // (big-endian: qubit q -> bit 11-q)
    j ^= ((j >> 0) & 1u) << 4;    // (c=11, t=7)
    j ^= ((j >> 6) & 1u) << 9;    // (c=5,  t=2)
    j ^= ((j >> 9) & 1u) << 8;    // (c=2,  t=3)
    j ^= ((j >> 11) & 1u) << 10;  // (c=0,  t=1)
    return j;
}

#define NCHUNK (1u << 19)   // total 32B chunks (2*4096*512 floats / 8)

__global__ __launch_bounds__(1024) void cnot_perm_copy_pers(
    const float* __restrict__ in, float* __restrict__ out)
{
    const unsigned nt = gridDim.x * blockDim.x;              // total threads
    for (unsigned idx = blockIdx.x * blockDim.x + threadIdx.x;
         idx < NCHUNK; idx += nt)
    {
        unsigned c8  = idx & 63u;        // 32B chunk within row
        unsigned row = idx >> 6;         // 0 .. 8191
        unsigned i   = row & 4095u;
        unsigned n   = row >> 12;
        unsigned src = (n << 12) | src_index(i);

        const float* gsrc = in  + ((size_t)src * 512u + c8 * 8u);
        float*       gdst = out + ((size_t)row * 512u + c8 * 8u);

        float v0,v1,v2,v3,v4,v5,v6,v7;
        asm volatile("ld.global.nc.v8.f32 {%0,%1,%2,%3,%4,%5,%6,%7}, [%8];"
            : "=f"(v0),"=f"(v1),"=f"(v2),"=f"(v3),
              "=f"(v4),"=f"(v5),"=f"(v6),"=f"(v7) : "l"(gsrc));
        asm volatile("st.global.v8.f32 [%0], {%1,%2,%3,%4,%5,%6,%7,%8};"
            :: "l"(gdst),
               "f"(v0),"f"(v1),"f"(v2),"f"(v3),
               "f"(v4),"f"(v5),"f"(v6),"f"(v7) : "memory");
    }
}

extern "C" void kernel_launch(void* const* d_in, const int* in_sizes, int n_in,
                              void* d_out, int out_size) {
    const float* in  = (const float*)d_in[0];
    float*       out = (float*)d_out;
    // One persistent CTA per SM (148 SMs on B300 die; GB300 has 152 — 148
    // still covers the chunk space via grid-stride).
    cnot_perm_copy_pers<<<148, 1024>>>(in, out);
}

// round 14
// speedup vs baseline: 1.0296x; 1.0296x over previous
#include <cuda_runtime.h>
#include <cstdint>

// state: [2, 4096, 512] float32. The 4 CNOTs compose into one bit-twiddle
// permutation of the 4096 row indices. GATHER: out[n,i,:] = in[n,src(i),:],
// rows = 512 floats = 2048 B contiguous.
//
// R12: R7 shape (1024x256, v8.f32, MLP=2) but ADJACENT chunks per thread:
// each thread moves 64 contiguous bytes, so one warp round = exactly one
// full 2 KB row on both load and store sides (single contiguous burst,
// one row address in flight per warp access).

static __device__ __forceinline__ unsigned src_index(unsigned j) {
    // PAIRS [(0,1),(2,3),(5,2),(11,7)] applied in reverse for the source map
    // (big-endian: qubit q -> bit 11-q)
    j ^= ((j >> 0) & 1u) << 4;    // (c=11, t=7)
    j ^= ((j >> 6) & 1u) << 9;    // (c=5,  t=2)
    j ^= ((j >> 9) & 1u) << 8;    // (c=2,  t=3)
    j ^= ((j >> 11) & 1u) << 10;  // (c=0,  t=1)
    return j;
}

// 2^19 v8 (32B) chunks total = 2^18 64B units. 1024 blocks x 256 threads,
// one 64B unit per thread. Warp lane l covers bytes [l*64, l*64+64) of one
// row: 32 lanes x 64B = 2048B = exactly one row.
__global__ __launch_bounds__(256) void cnot_perm_copy_v8adj(
    const float* __restrict__ in, float* __restrict__ out)
{
    unsigned t   = blockIdx.x * blockDim.x + threadIdx.x;  // 0 .. 2^18-1
    unsigned c16 = t & 31u;          // 64B unit within row (32 per row)
    unsigned row = t >> 5;           // 0 .. 8191
    unsigned i   = row & 4095u;
    unsigned n   = row >> 12;
    unsigned src = (n << 12) | src_index(i);

    const float* gsrc = in  + ((size_t)src * 512u + c16 * 16u);
    float*       gdst = out + ((size_t)row * 512u + c16 * 16u);

    float a0,a1,a2,a3,a4,a5,a6,a7;
    float b0,b1,b2,b3,b4,b5,b6,b7;
    asm volatile("ld.global.nc.v8.f32 {%0,%1,%2,%3,%4,%5,%6,%7}, [%8];"
        : "=f"(a0),"=f"(a1),"=f"(a2),"=f"(a3),
          "=f"(a4),"=f"(a5),"=f"(a6),"=f"(a7) : "l"(gsrc));
    asm volatile("ld.global.nc.v8.f32 {%0,%1,%2,%3,%4,%5,%6,%7}, [%8];"
        : "=f"(b0),"=f"(b1),"=f"(b2),"=f"(b3),
          "=f"(b4),"=f"(b5),"=f"(b6),"=f"(b7) : "l"(gsrc + 8));
    asm volatile("st.global.v8.f32 [%0], {%1,%2,%3,%4,%5,%6,%7,%8};"
        :: "l"(gdst),
           "f"(a0),"f"(a1),"f"(a2),"f"(a3),
           "f"(a4),"f"(a5),"f"(a6),"f"(a7) : "memory");
    asm volatile("st.global.v8.f32 [%0], {%1,%2,%3,%4,%5,%6,%7,%8};"
        :: "l"(gdst + 8),
           "f"(b0),"f"(b1),"f"(b2),"f"(b3),
           "f"(b4),"f"(b5),"f"(b6),"f"(b7) : "memory");
}

extern "C" void kernel_launch(void* const* d_in, const int* in_sizes, int n_in,
                              void* d_out, int out_size) {
    const float* in  = (const float*)d_in[0];
    float*       out = (float*)d_out;
    // 2^18 64B units / 256 threads = 1024 blocks (single wave)
    cnot_perm_copy_v8adj<<<1024, 256>>>(in, out);
}